// round 15
// baseline (speedup 1.0000x reference)
#include <cuda_runtime.h>
#include <math_constants.h>

// Fixed shapes
#define B      32
#define C0     512
#define C1     1024
#define HW0    1444      // 38*38, divisible by 4
#define HW4_0  361       // HW0/4 in float4 units
#define HW1    361       // 19*19
#define THRESH 0.15f
#define NCH0   8         // channel chunks, level 0 (CPC = 64)
#define NCH1   16        // channel chunks, level 1 (CPC = 64)
#define CPC0   (C0/NCH0) // 64
#define CPC1   (C1/NCH1) // 64

// Output layout (float32): fw[2], embT0, embT1, embS0, embS1
#define OFF_FW  0
#define OFF_ET0 2
#define OFF_ET1 (OFF_ET0 + B*HW0)
#define OFF_ES0 (OFF_ET1 + B*HW1)
#define OFF_ES1 (OFF_ES0 + B*HW0)

// Static device scratch
__device__ float  d_w0[B * C0];
__device__ float  d_w1[B * C1];
__device__ float  d_pc0[NCH0 * B * HW0];
__device__ float  d_pt0[NCH0 * B * HW0];
__device__ float  d_ps0[NCH0 * B * HW0];
__device__ float  d_pc1[NCH1 * B * HW1];
__device__ float  d_pt1[NCH1 * B * HW1];
__device__ float  d_ps1[NCH1 * B * HW1];
__device__ float4 d_cam0[B * HW4_0];   // combined cam, level 0
__device__ float  d_cam1[B * HW1];     // combined cam, level 1
__device__ float  d_pmax[2 * B];
__device__ float  d_psum[2 * B];
__device__ float  d_thr[2 * B];
__device__ int    d_cnt = 0;

// ---------------------------------------------------------------------------
// Phase A (R11 proven): gmean (g0+g1) AND Sf channel-sum partials,
// interleaved period-25 (16 gmean + 9 Sf). 6400 blocks x 128.
// ---------------------------------------------------------------------------
__global__ __launch_bounds__(128)
void k_phaseA(const float* __restrict__ g0, const float* __restrict__ g1,
              const float* __restrict__ Sf0, const float* __restrict__ Sf1,
              float* __restrict__ w0, float* __restrict__ w1,
              float* __restrict__ ps0, float* __restrict__ ps1) {
    const int grp = blockIdx.x / 25;
    const int r   = blockIdx.x % 25;

    if (r < 16) {
        const int gblk = grp * 16 + r;          // 0..4095
        const int lane = threadIdx.x & 31;
        const int warp = threadIdx.x >> 5;

        if (gblk < 2048) {
            const int pair = gblk * 4 + warp;
            const float4* p0 = reinterpret_cast<const float4*>(g0) + (size_t)(2 * pair) * HW4_0;
            const float4* p1 = p0 + HW4_0;
            float4 a0 = {0,0,0,0}, a1 = {0,0,0,0};
            #pragma unroll 2
            for (int i = lane; i < HW4_0; i += 32) {
                float4 v0 = __ldcs(p0 + i);
                float4 v1 = __ldcs(p1 + i);
                a0.x += v0.x; a0.y += v0.y; a0.z += v0.z; a0.w += v0.w;
                a1.x += v1.x; a1.y += v1.y; a1.z += v1.z; a1.w += v1.w;
            }
            float s0 = (a0.x + a0.y) + (a0.z + a0.w);
            float s1 = (a1.x + a1.y) + (a1.z + a1.w);
            #pragma unroll
            for (int o = 16; o; o >>= 1) {
                s0 += __shfl_xor_sync(0xffffffffu, s0, o);
                s1 += __shfl_xor_sync(0xffffffffu, s1, o);
            }
            if (lane == 0) {
                w0[2 * pair]     = s0 * (1.f / HW0);
                w0[2 * pair + 1] = s1 * (1.f / HW0);
            }
        } else {
            const int quad = (gblk - 2048) * 4 + warp;
            const float* p = g1 + (size_t)(4 * quad) * HW1;
            float s0 = 0.f, s1 = 0.f, s2 = 0.f, s3 = 0.f;
            #pragma unroll 2
            for (int i = lane; i < HW1; i += 32) {
                s0 += __ldcs(p + i);
                s1 += __ldcs(p + HW1 + i);
                s2 += __ldcs(p + 2 * HW1 + i);
                s3 += __ldcs(p + 3 * HW1 + i);
            }
            #pragma unroll
            for (int o = 16; o; o >>= 1) {
                s0 += __shfl_xor_sync(0xffffffffu, s0, o);
                s1 += __shfl_xor_sync(0xffffffffu, s1, o);
                s2 += __shfl_xor_sync(0xffffffffu, s2, o);
                s3 += __shfl_xor_sync(0xffffffffu, s3, o);
            }
            if (lane == 0) {
                const float inv = 1.f / HW1;
                w1[4 * quad]     = s0 * inv;
                w1[4 * quad + 1] = s1 * inv;
                w1[4 * quad + 2] = s2 * inv;
                w1[4 * quad + 3] = s3 * inv;
            }
        }
    } else {
        const int sblk = grp * 9 + (r - 16);    // 0..2303
        const int tid  = threadIdx.x;

        if (sblk < 768) {
            const int x = sblk % 3, b = (sblk / 3) % 32, chunk = sblk / 96;
            const int q = x * 128 + tid;
            if (q >= HW4_0) return;
            const float4* sp = reinterpret_cast<const float4*>(Sf0)
                             + (size_t)(b * C0 + chunk * CPC0) * HW4_0 + q;
            float4 acc = {0,0,0,0};
            #pragma unroll 8
            for (int c = 0; c < CPC0; ++c) {
                float4 s = __ldcs(sp + (size_t)c * HW4_0);
                acc.x += s.x; acc.y += s.y; acc.z += s.z; acc.w += s.w;
            }
            reinterpret_cast<float4*>(ps0)[(size_t)(chunk * B + b) * HW4_0 + q] = acc;
        } else {
            const int t = sblk - 768;           // 0..1535
            const int x = t % 3, b = (t / 3) % 32, chunk = t / 96;
            const int hw = x * 128 + tid;
            if (hw >= HW1) return;
            const float* sp = Sf1 + (size_t)(b * C1 + chunk * CPC1) * HW1 + hw;
            float acc = 0.f;
            #pragma unroll 8
            for (int c = 0; c < CPC1; ++c) acc += __ldcs(sp + (size_t)c * HW1);
            ps1[(size_t)(chunk * B + b) * HW1 + hw] = acc;
        }
    }
}

// ---------------------------------------------------------------------------
// Phase B (R11 proven): Tf-only pass -> pc (weighted) and pt (plain sums).
// grid (3, B, NCH0+NCH1) = 2304 blocks x 128.
// ---------------------------------------------------------------------------
__global__ __launch_bounds__(128)
void k_camT(const float* __restrict__ Tf0, const float* __restrict__ w0,
            float* __restrict__ pc0, float* __restrict__ pt0,
            const float* __restrict__ Tf1, const float* __restrict__ w1,
            float* __restrict__ pc1, float* __restrict__ pt1) {
    __shared__ float sw[64];
    const int b = blockIdx.y, z = blockIdx.z, tid = threadIdx.x;

    if (z < NCH0) {
        const int chunk = z;
        if (tid < CPC0) sw[tid] = w0[b * C0 + chunk * CPC0 + tid];
        __syncthreads();

        const int q = blockIdx.x * 128 + tid;
        if (q >= HW4_0) return;
        const float4* tp = reinterpret_cast<const float4*>(Tf0)
                         + (size_t)(b * C0 + chunk * CPC0) * HW4_0 + q;
        float4 ac = {0,0,0,0}, at = {0,0,0,0};
        #pragma unroll 8
        for (int c = 0; c < CPC0; ++c) {
            float4 t = __ldcs(tp + (size_t)c * HW4_0);
            const float wv = sw[c];
            ac.x = fmaf(wv, t.x, ac.x); ac.y = fmaf(wv, t.y, ac.y);
            ac.z = fmaf(wv, t.z, ac.z); ac.w = fmaf(wv, t.w, ac.w);
            at.x += t.x; at.y += t.y; at.z += t.z; at.w += t.w;
        }
        const size_t o = (size_t)(chunk * B + b) * HW4_0 + q;
        reinterpret_cast<float4*>(pc0)[o] = ac;
        reinterpret_cast<float4*>(pt0)[o] = at;
    } else {
        const int chunk = z - NCH0;
        if (tid < CPC1) sw[tid] = w1[b * C1 + chunk * CPC1 + tid];
        __syncthreads();

        const int hw = blockIdx.x * 128 + tid;
        if (hw >= HW1) return;
        const float* tp = Tf1 + (size_t)(b * C1 + chunk * CPC1) * HW1 + hw;
        float ac = 0.f, at = 0.f;
        #pragma unroll 8
        for (int c = 0; c < CPC1; ++c) {
            float t = __ldcs(tp + (size_t)c * HW1);
            ac = fmaf(sw[c], t, ac);
            at += t;
        }
        const size_t o = (size_t)(chunk * B + b) * HW1 + hw;
        pc1[o] = ac; pt1[o] = at;
    }
}

// ---------------------------------------------------------------------------
// Phase C1 (R13 proven): combine pc chunks -> cam, per-b max + clipped sum.
// 64 blocks x 512. Last-arriving block computes thresholds, scores, fw.
// ---------------------------------------------------------------------------
__global__ __launch_bounds__(512)
void k_camstat(const float* __restrict__ pc0, const float* __restrict__ pc1,
               float* __restrict__ out) {
    __shared__ float smx[512], ssm[512];
    __shared__ float sscore[64];
    __shared__ int   sflag;
    const int t = threadIdx.x;

    float mx = -CUDART_INF_F, sm = 0.f;
    if (blockIdx.x < 32) {
        const int b = blockIdx.x;
        if (t < HW4_0) {
            float4 cc = {0,0,0,0};
            #pragma unroll
            for (int ch = 0; ch < NCH0; ++ch) {
                const float4 v = reinterpret_cast<const float4*>(pc0)
                                    [(size_t)(ch * B + b) * HW4_0 + t];
                cc.x += v.x; cc.y += v.y; cc.z += v.z; cc.w += v.w;
            }
            d_cam0[b * HW4_0 + t] = cc;
            mx = fmaxf(fmaxf(cc.x, cc.y), fmaxf(cc.z, cc.w));
            sm = fmaxf(cc.x, 0.f) + fmaxf(cc.y, 0.f) + fmaxf(cc.z, 0.f) + fmaxf(cc.w, 0.f);
        }
    } else {
        const int b = blockIdx.x - 32;
        if (t < HW1) {
            float cc = 0.f;
            #pragma unroll
            for (int ch = 0; ch < NCH1; ++ch)
                cc += pc1[(size_t)(ch * B + b) * HW1 + t];
            d_cam1[b * HW1 + t] = cc;
            mx = cc;
            sm = fmaxf(cc, 0.f);
        }
    }

    smx[t] = mx; ssm[t] = sm;
    __syncthreads();
    #pragma unroll
    for (int s = 256; s; s >>= 1) {
        if (t < s) { smx[t] = fmaxf(smx[t], smx[t + s]); ssm[t] += ssm[t + s]; }
        __syncthreads();
    }
    if (t == 0) {
        d_pmax[blockIdx.x] = smx[0];
        d_psum[blockIdx.x] = ssm[0];
        __threadfence();
        const int old = atomicAdd(&d_cnt, 1);
        sflag = (old == 63);
        if (sflag) d_cnt = 0;
    }
    __syncthreads();
    if (!sflag) return;

    if (t < 64) {
        __threadfence();
        const float inv = (t < 32) ? (1.f / HW0) : (1.f / HW1);
        sscore[t] = d_psum[t] * inv;
        d_thr[t]  = fabsf(d_pmax[t] * THRESH);
    }
    __syncthreads();
    if (t == 0) {
        float s0 = 0.f, s1 = 0.f;
        for (int i = 0; i < 32; ++i) { s0 += sscore[i]; s1 += sscore[32 + i]; }
        const float invT = 1.f / (s0 + s1);
        out[OFF_FW + 0] = s0 * invT;
        out[OFF_FW + 1] = s1 * invT;
    }
}

// ---------------------------------------------------------------------------
// Phase C2: mask + write outputs, 4 threads per pixel (chunk-split + shfl).
// 362 blocks x 256: bids [0,181): level 0; [181,362): level 1.
// Shfls are executed by ALL lanes unconditionally (zeros for invalid lanes).
// ---------------------------------------------------------------------------
__global__ __launch_bounds__(256)
void k_mask(const float* __restrict__ pt0, const float* __restrict__ ps0,
            const float* __restrict__ pt1, const float* __restrict__ ps1,
            float* __restrict__ out) {
    const int t   = threadIdx.x;
    const int sub = t & 3;

    if (blockIdx.x < 181) {
        // -------- level 0: pixel = one float4 group --------
        const int gi    = blockIdx.x * 64 + (t >> 2);   // f4-pixel index 0..11583
        const bool valid = gi < B * HW4_0;
        const int b = valid ? gi / HW4_0 : 0;
        const int q = valid ? gi % HW4_0 : 0;

        float4 tt = {0,0,0,0}, ss = {0,0,0,0};
        if (valid) {
            #pragma unroll
            for (int k = 0; k < 2; ++k) {           // 2 of 8 chunks per sub
                const int ch = sub * 2 + k;
                const size_t o = (size_t)(ch * B + b) * HW4_0 + q;
                const float4 tv = reinterpret_cast<const float4*>(pt0)[o];
                const float4 sv = reinterpret_cast<const float4*>(ps0)[o];
                tt.x += tv.x; tt.y += tv.y; tt.z += tv.z; tt.w += tv.w;
                ss.x += sv.x; ss.y += sv.y; ss.z += sv.z; ss.w += sv.w;
            }
        }
        #pragma unroll
        for (int o2 = 1; o2 < 4; o2 <<= 1) {        // ALL lanes execute
            tt.x += __shfl_xor_sync(0xffffffffu, tt.x, o2);
            tt.y += __shfl_xor_sync(0xffffffffu, tt.y, o2);
            tt.z += __shfl_xor_sync(0xffffffffu, tt.z, o2);
            tt.w += __shfl_xor_sync(0xffffffffu, tt.w, o2);
            ss.x += __shfl_xor_sync(0xffffffffu, ss.x, o2);
            ss.y += __shfl_xor_sync(0xffffffffu, ss.y, o2);
            ss.z += __shfl_xor_sync(0xffffffffu, ss.z, o2);
            ss.w += __shfl_xor_sync(0xffffffffu, ss.w, o2);
        }
        if (sub == 0 && valid) {
            const float  thr = d_thr[b];
            const float4 cc  = d_cam0[gi];
            constexpr float invC = 1.f / (float)C0;
            float* oT = out + OFF_ET0 + (size_t)b * HW0 + 4 * q;
            float* oS = out + OFF_ES0 + (size_t)b * HW0 + 4 * q;
            float2 t01 = { cc.x > thr ? tt.x * invC : 0.f, cc.y > thr ? tt.y * invC : 0.f };
            float2 t23 = { cc.z > thr ? tt.z * invC : 0.f, cc.w > thr ? tt.w * invC : 0.f };
            float2 s01 = { cc.x > thr ? ss.x * invC : 0.f, cc.y > thr ? ss.y * invC : 0.f };
            float2 s23 = { cc.z > thr ? ss.z * invC : 0.f, cc.w > thr ? ss.w * invC : 0.f };
            *reinterpret_cast<float2*>(oT)     = t01;
            *reinterpret_cast<float2*>(oT + 2) = t23;
            *reinterpret_cast<float2*>(oS)     = s01;
            *reinterpret_cast<float2*>(oS + 2) = s23;
        }
    } else {
        // -------- level 1: pixel = one scalar --------
        const int gi    = (blockIdx.x - 181) * 64 + (t >> 2);  // 0..11583
        const bool valid = gi < B * HW1;
        const int b  = valid ? gi / HW1 : 0;
        const int px = valid ? gi % HW1 : 0;

        float tt = 0.f, ss = 0.f;
        if (valid) {
            #pragma unroll
            for (int k = 0; k < 4; ++k) {           // 4 of 16 chunks per sub
                const int ch = sub * 4 + k;
                const size_t o = (size_t)(ch * B + b) * HW1 + px;
                tt += pt1[o];
                ss += ps1[o];
            }
        }
        #pragma unroll
        for (int o2 = 1; o2 < 4; o2 <<= 1) {        // ALL lanes execute
            tt += __shfl_xor_sync(0xffffffffu, tt, o2);
            ss += __shfl_xor_sync(0xffffffffu, ss, o2);
        }
        if (sub == 0 && valid) {
            const float thr = d_thr[32 + b];
            const float cc  = d_cam1[gi];
            constexpr float invC = 1.f / (float)C1;
            const bool mk = cc > thr;
            out[OFF_ET1 + gi] = mk ? tt * invC : 0.f;
            out[OFF_ES1 + gi] = mk ? ss * invC : 0.f;
        }
    }
}

// ---------------------------------------------------------------------------
extern "C" void kernel_launch(void* const* d_in, const int* in_sizes, int n_in,
                              void* d_out, int out_size) {
    const float* Tf0 = (const float*)d_in[0];
    const float* Tf1 = (const float*)d_in[1];
    const float* Sf0 = (const float*)d_in[2];
    const float* Sf1 = (const float*)d_in[3];
    const float* g0  = (const float*)d_in[4];
    const float* g1  = (const float*)d_in[5];
    float* out = (float*)d_out;

    float *w0, *w1, *pc0, *pt0, *ps0, *pc1, *pt1, *ps1;
    cudaGetSymbolAddress((void**)&w0,  d_w0);
    cudaGetSymbolAddress((void**)&w1,  d_w1);
    cudaGetSymbolAddress((void**)&pc0, d_pc0);
    cudaGetSymbolAddress((void**)&pt0, d_pt0);
    cudaGetSymbolAddress((void**)&ps0, d_ps0);
    cudaGetSymbolAddress((void**)&pc1, d_pc1);
    cudaGetSymbolAddress((void**)&pt1, d_pt1);
    cudaGetSymbolAddress((void**)&ps1, d_ps1);

    // Phase A: gmean + Sf sums, interleaved blocks (284 MB)
    k_phaseA<<<6400, 128>>>(g0, g1, Sf0, Sf1, w0, w1, ps0, ps1);

    // Phase B: Tf pass -> pc, pt (142 MB)
    {
        dim3 grid(3, B, NCH0 + NCH1);   // 2304 blocks of 128
        k_camT<<<grid, 128>>>(Tf0, w0, pc0, pt0, Tf1, w1, pc1, pt1);
    }

    // Phase C1: cam combine + stats + thresholds + fw
    k_camstat<<<64, 512>>>(pc0, pc1, out);

    // Phase C2: mask + outputs (4 threads/pixel)
    k_mask<<<362, 256>>>(pt0, ps0, pt1, ps1, out);
}

// round 16
// speedup vs baseline: 1.0136x; 1.0136x over previous
#include <cuda_runtime.h>
#include <math_constants.h>

// Fixed shapes
#define B      32
#define C0     512
#define C1     1024
#define HW0    1444      // 38*38, divisible by 4
#define HW4_0  361       // HW0/4 in float4 units
#define HW1    361       // 19*19
#define THRESH 0.15f
#define NCH0   8         // channel chunks, level 0 (CPC = 64)
#define NCH1   16        // channel chunks, level 1 (CPC = 64)
#define CPC0   (C0/NCH0) // 64
#define CPC1   (C1/NCH1) // 64

// Output layout (float32): fw[2], embT0, embT1, embS0, embS1
#define OFF_FW  0
#define OFF_ET0 2
#define OFF_ET1 (OFF_ET0 + B*HW0)
#define OFF_ES0 (OFF_ET1 + B*HW1)
#define OFF_ES1 (OFF_ES0 + B*HW0)

// Static device scratch
__device__ float  d_w0[B * C0];
__device__ float  d_w1[B * C1];
__device__ float  d_pc0[NCH0 * B * HW0];
__device__ float  d_pt0[NCH0 * B * HW0];
__device__ float  d_ps0[NCH0 * B * HW0];
__device__ float  d_pc1[NCH1 * B * HW1];
__device__ float  d_pt1[NCH1 * B * HW1];
__device__ float  d_ps1[NCH1 * B * HW1];
__device__ float4 d_cam0[B * HW4_0];   // combined cam, level 0
__device__ float  d_cam1[B * HW1];     // combined cam, level 1
__device__ float  d_pmax[2 * B];
__device__ float  d_psum[2 * B];
__device__ float  d_thr[2 * B];
__device__ int    d_cnt = 0;

// ---------------------------------------------------------------------------
// Phase A (R11 proven): gmean (g0+g1) AND Sf channel-sum partials,
// interleaved period-25 (16 gmean + 9 Sf). 6400 blocks x 128.
// ---------------------------------------------------------------------------
__global__ __launch_bounds__(128)
void k_phaseA(const float* __restrict__ g0, const float* __restrict__ g1,
              const float* __restrict__ Sf0, const float* __restrict__ Sf1,
              float* __restrict__ w0, float* __restrict__ w1,
              float* __restrict__ ps0, float* __restrict__ ps1) {
    const int grp = blockIdx.x / 25;
    const int r   = blockIdx.x % 25;

    if (r < 16) {
        const int gblk = grp * 16 + r;          // 0..4095
        const int lane = threadIdx.x & 31;
        const int warp = threadIdx.x >> 5;

        if (gblk < 2048) {
            const int pair = gblk * 4 + warp;
            const float4* p0 = reinterpret_cast<const float4*>(g0) + (size_t)(2 * pair) * HW4_0;
            const float4* p1 = p0 + HW4_0;
            float4 a0 = {0,0,0,0}, a1 = {0,0,0,0};
            #pragma unroll 2
            for (int i = lane; i < HW4_0; i += 32) {
                float4 v0 = __ldcs(p0 + i);
                float4 v1 = __ldcs(p1 + i);
                a0.x += v0.x; a0.y += v0.y; a0.z += v0.z; a0.w += v0.w;
                a1.x += v1.x; a1.y += v1.y; a1.z += v1.z; a1.w += v1.w;
            }
            float s0 = (a0.x + a0.y) + (a0.z + a0.w);
            float s1 = (a1.x + a1.y) + (a1.z + a1.w);
            #pragma unroll
            for (int o = 16; o; o >>= 1) {
                s0 += __shfl_xor_sync(0xffffffffu, s0, o);
                s1 += __shfl_xor_sync(0xffffffffu, s1, o);
            }
            if (lane == 0) {
                w0[2 * pair]     = s0 * (1.f / HW0);
                w0[2 * pair + 1] = s1 * (1.f / HW0);
            }
        } else {
            const int quad = (gblk - 2048) * 4 + warp;
            const float* p = g1 + (size_t)(4 * quad) * HW1;
            float s0 = 0.f, s1 = 0.f, s2 = 0.f, s3 = 0.f;
            #pragma unroll 2
            for (int i = lane; i < HW1; i += 32) {
                s0 += __ldcs(p + i);
                s1 += __ldcs(p + HW1 + i);
                s2 += __ldcs(p + 2 * HW1 + i);
                s3 += __ldcs(p + 3 * HW1 + i);
            }
            #pragma unroll
            for (int o = 16; o; o >>= 1) {
                s0 += __shfl_xor_sync(0xffffffffu, s0, o);
                s1 += __shfl_xor_sync(0xffffffffu, s1, o);
                s2 += __shfl_xor_sync(0xffffffffu, s2, o);
                s3 += __shfl_xor_sync(0xffffffffu, s3, o);
            }
            if (lane == 0) {
                const float inv = 1.f / HW1;
                w1[4 * quad]     = s0 * inv;
                w1[4 * quad + 1] = s1 * inv;
                w1[4 * quad + 2] = s2 * inv;
                w1[4 * quad + 3] = s3 * inv;
            }
        }
    } else {
        const int sblk = grp * 9 + (r - 16);    // 0..2303
        const int tid  = threadIdx.x;

        if (sblk < 768) {
            const int x = sblk % 3, b = (sblk / 3) % 32, chunk = sblk / 96;
            const int q = x * 128 + tid;
            if (q >= HW4_0) return;
            const float4* sp = reinterpret_cast<const float4*>(Sf0)
                             + (size_t)(b * C0 + chunk * CPC0) * HW4_0 + q;
            float4 acc = {0,0,0,0};
            #pragma unroll 8
            for (int c = 0; c < CPC0; ++c) {
                float4 s = __ldcs(sp + (size_t)c * HW4_0);
                acc.x += s.x; acc.y += s.y; acc.z += s.z; acc.w += s.w;
            }
            reinterpret_cast<float4*>(ps0)[(size_t)(chunk * B + b) * HW4_0 + q] = acc;
        } else {
            const int t = sblk - 768;           // 0..1535
            const int x = t % 3, b = (t / 3) % 32, chunk = t / 96;
            const int hw = x * 128 + tid;
            if (hw >= HW1) return;
            const float* sp = Sf1 + (size_t)(b * C1 + chunk * CPC1) * HW1 + hw;
            float acc = 0.f;
            #pragma unroll 8
            for (int c = 0; c < CPC1; ++c) acc += __ldcs(sp + (size_t)c * HW1);
            ps1[(size_t)(chunk * B + b) * HW1 + hw] = acc;
        }
    }
}

// ---------------------------------------------------------------------------
// Phase B (R11 proven): Tf-only pass -> pc (weighted) and pt (plain sums).
// grid (3, B, NCH0+NCH1) = 2304 blocks x 128.
// ---------------------------------------------------------------------------
__global__ __launch_bounds__(128)
void k_camT(const float* __restrict__ Tf0, const float* __restrict__ w0,
            float* __restrict__ pc0, float* __restrict__ pt0,
            const float* __restrict__ Tf1, const float* __restrict__ w1,
            float* __restrict__ pc1, float* __restrict__ pt1) {
    __shared__ float sw[64];
    const int b = blockIdx.y, z = blockIdx.z, tid = threadIdx.x;

    if (z < NCH0) {
        const int chunk = z;
        if (tid < CPC0) sw[tid] = w0[b * C0 + chunk * CPC0 + tid];
        __syncthreads();

        const int q = blockIdx.x * 128 + tid;
        if (q >= HW4_0) return;
        const float4* tp = reinterpret_cast<const float4*>(Tf0)
                         + (size_t)(b * C0 + chunk * CPC0) * HW4_0 + q;
        float4 ac = {0,0,0,0}, at = {0,0,0,0};
        #pragma unroll 8
        for (int c = 0; c < CPC0; ++c) {
            float4 t = __ldcs(tp + (size_t)c * HW4_0);
            const float wv = sw[c];
            ac.x = fmaf(wv, t.x, ac.x); ac.y = fmaf(wv, t.y, ac.y);
            ac.z = fmaf(wv, t.z, ac.z); ac.w = fmaf(wv, t.w, ac.w);
            at.x += t.x; at.y += t.y; at.z += t.z; at.w += t.w;
        }
        const size_t o = (size_t)(chunk * B + b) * HW4_0 + q;
        reinterpret_cast<float4*>(pc0)[o] = ac;
        reinterpret_cast<float4*>(pt0)[o] = at;
    } else {
        const int chunk = z - NCH0;
        if (tid < CPC1) sw[tid] = w1[b * C1 + chunk * CPC1 + tid];
        __syncthreads();

        const int hw = blockIdx.x * 128 + tid;
        if (hw >= HW1) return;
        const float* tp = Tf1 + (size_t)(b * C1 + chunk * CPC1) * HW1 + hw;
        float ac = 0.f, at = 0.f;
        #pragma unroll 8
        for (int c = 0; c < CPC1; ++c) {
            float t = __ldcs(tp + (size_t)c * HW1);
            ac = fmaf(sw[c], t, ac);
            at += t;
        }
        const size_t o = (size_t)(chunk * B + b) * HW1 + hw;
        pc1[o] = ac; pt1[o] = at;
    }
}

// ---------------------------------------------------------------------------
// Phase C1 (merged): 246 blocks x 512.
//  bids [0,64): stat blocks — pc->cam, max/clipped-sum, thr; last does fw.
//  bids [64,155): level-0 combine — pt/ps sums, 4 thr/pixel, UNMASKED write.
//  bids [155,246): level-1 combine — same for level 1.
// Stat and combine are independent (mask applied later by k_maskzero).
// ---------------------------------------------------------------------------
__global__ __launch_bounds__(512)
void k_finC1(const float* __restrict__ pc0, const float* __restrict__ pc1,
             const float* __restrict__ pt0, const float* __restrict__ ps0,
             const float* __restrict__ pt1, const float* __restrict__ ps1,
             float* __restrict__ out) {
    const int t = threadIdx.x;

    if (blockIdx.x < 64) {
        // ================= stat block: one (level,b) =================
        __shared__ float smx[512], ssm[512];
        __shared__ float sscore[64];
        __shared__ int   sflag;

        float mx = -CUDART_INF_F, sm = 0.f;
        if (blockIdx.x < 32) {
            const int b = blockIdx.x;
            if (t < HW4_0) {
                float4 cc = {0,0,0,0};
                #pragma unroll
                for (int ch = 0; ch < NCH0; ++ch) {
                    const float4 v = reinterpret_cast<const float4*>(pc0)
                                        [(size_t)(ch * B + b) * HW4_0 + t];
                    cc.x += v.x; cc.y += v.y; cc.z += v.z; cc.w += v.w;
                }
                d_cam0[b * HW4_0 + t] = cc;
                mx = fmaxf(fmaxf(cc.x, cc.y), fmaxf(cc.z, cc.w));
                sm = fmaxf(cc.x, 0.f) + fmaxf(cc.y, 0.f) + fmaxf(cc.z, 0.f) + fmaxf(cc.w, 0.f);
            }
        } else {
            const int b = blockIdx.x - 32;
            if (t < HW1) {
                float cc = 0.f;
                #pragma unroll
                for (int ch = 0; ch < NCH1; ++ch)
                    cc += pc1[(size_t)(ch * B + b) * HW1 + t];
                d_cam1[b * HW1 + t] = cc;
                mx = cc;
                sm = fmaxf(cc, 0.f);
            }
        }

        smx[t] = mx; ssm[t] = sm;
        __syncthreads();
        #pragma unroll
        for (int s = 256; s; s >>= 1) {
            if (t < s) { smx[t] = fmaxf(smx[t], smx[t + s]); ssm[t] += ssm[t + s]; }
            __syncthreads();
        }
        if (t == 0) {
            d_pmax[blockIdx.x] = smx[0];
            d_psum[blockIdx.x] = ssm[0];
            d_thr[blockIdx.x]  = fabsf(smx[0] * THRESH);
            __threadfence();
            const int old = atomicAdd(&d_cnt, 1);
            sflag = (old == 63);
            if (sflag) d_cnt = 0;          // reset for graph replay
        }
        __syncthreads();
        if (!sflag) return;

        if (t < 64) {
            __threadfence();
            const float inv = (t < 32) ? (1.f / HW0) : (1.f / HW1);
            sscore[t] = d_psum[t] * inv;
        }
        __syncthreads();
        if (t == 0) {
            float s0 = 0.f, s1 = 0.f;
            for (int i = 0; i < 32; ++i) { s0 += sscore[i]; s1 += sscore[32 + i]; }
            const float invT = 1.f / (s0 + s1);
            out[OFF_FW + 0] = s0 * invT;
            out[OFF_FW + 1] = s1 * invT;
        }
        return;
    }

    // ================= combine blocks: unmasked emb means =================
    const int cid = blockIdx.x - 64;   // 0..181
    const int sub = t & 3;

    if (cid < 91) {
        // -------- level 0: 128 f4-pixels per block, 4 thr each --------
        const int gi    = cid * 128 + (t >> 2);   // f4-pixel 0..11647
        const bool valid = gi < B * HW4_0;
        const int b = valid ? gi / HW4_0 : 0;
        const int q = valid ? gi % HW4_0 : 0;

        float4 tt = {0,0,0,0}, ss = {0,0,0,0};
        if (valid) {
            #pragma unroll
            for (int k = 0; k < 2; ++k) {
                const int ch = sub * 2 + k;
                const size_t o = (size_t)(ch * B + b) * HW4_0 + q;
                const float4 tv = reinterpret_cast<const float4*>(pt0)[o];
                const float4 sv = reinterpret_cast<const float4*>(ps0)[o];
                tt.x += tv.x; tt.y += tv.y; tt.z += tv.z; tt.w += tv.w;
                ss.x += sv.x; ss.y += sv.y; ss.z += sv.z; ss.w += sv.w;
            }
        }
        #pragma unroll
        for (int o2 = 1; o2 < 4; o2 <<= 1) {      // ALL lanes execute
            tt.x += __shfl_xor_sync(0xffffffffu, tt.x, o2);
            tt.y += __shfl_xor_sync(0xffffffffu, tt.y, o2);
            tt.z += __shfl_xor_sync(0xffffffffu, tt.z, o2);
            tt.w += __shfl_xor_sync(0xffffffffu, tt.w, o2);
            ss.x += __shfl_xor_sync(0xffffffffu, ss.x, o2);
            ss.y += __shfl_xor_sync(0xffffffffu, ss.y, o2);
            ss.z += __shfl_xor_sync(0xffffffffu, ss.z, o2);
            ss.w += __shfl_xor_sync(0xffffffffu, ss.w, o2);
        }
        if (sub == 0 && valid) {
            constexpr float invC = 1.f / (float)C0;
            float* oT = out + OFF_ET0 + (size_t)b * HW0 + 4 * q;
            float* oS = out + OFF_ES0 + (size_t)b * HW0 + 4 * q;
            float2 t01 = { tt.x * invC, tt.y * invC };
            float2 t23 = { tt.z * invC, tt.w * invC };
            float2 s01 = { ss.x * invC, ss.y * invC };
            float2 s23 = { ss.z * invC, ss.w * invC };
            *reinterpret_cast<float2*>(oT)     = t01;
            *reinterpret_cast<float2*>(oT + 2) = t23;
            *reinterpret_cast<float2*>(oS)     = s01;
            *reinterpret_cast<float2*>(oS + 2) = s23;
        }
    } else {
        // -------- level 1: 128 pixels per block, 4 thr each --------
        const int gi    = (cid - 91) * 128 + (t >> 2);  // 0..11647
        const bool valid = gi < B * HW1;
        const int b  = valid ? gi / HW1 : 0;
        const int px = valid ? gi % HW1 : 0;

        float tt = 0.f, ss = 0.f;
        if (valid) {
            #pragma unroll
            for (int k = 0; k < 4; ++k) {
                const int ch = sub * 4 + k;
                const size_t o = (size_t)(ch * B + b) * HW1 + px;
                tt += pt1[o];
                ss += ps1[o];
            }
        }
        #pragma unroll
        for (int o2 = 1; o2 < 4; o2 <<= 1) {      // ALL lanes execute
            tt += __shfl_xor_sync(0xffffffffu, tt, o2);
            ss += __shfl_xor_sync(0xffffffffu, ss, o2);
        }
        if (sub == 0 && valid) {
            constexpr float invC = 1.f / (float)C1;
            out[OFF_ET1 + gi] = tt * invC;
            out[OFF_ES1 + gi] = ss * invC;
        }
    }
}

// ---------------------------------------------------------------------------
// Phase C2: maskzero — one thread per pixel; zero emb entries where mask
// fails. 226 blocks x 256 (57760 pixels total across both levels).
// ---------------------------------------------------------------------------
__global__ __launch_bounds__(256)
void k_maskzero(float* __restrict__ out) {
    const int i = blockIdx.x * 256 + threadIdx.x;
    const float* cam0f = reinterpret_cast<const float*>(d_cam0);

    if (i < B * HW0) {
        // level 0: cam0f layout is exactly b*HW0 + e
        const int b = i / HW0;
        if (!(cam0f[i] > d_thr[b])) {
            out[OFF_ET0 + i] = 0.f;
            out[OFF_ES0 + i] = 0.f;
        }
    } else {
        const int j = i - B * HW0;
        if (j < B * HW1) {
            const int b = j / HW1;
            if (!(d_cam1[j] > d_thr[32 + b])) {
                out[OFF_ET1 + j] = 0.f;
                out[OFF_ES1 + j] = 0.f;
            }
        }
    }
}

// ---------------------------------------------------------------------------
extern "C" void kernel_launch(void* const* d_in, const int* in_sizes, int n_in,
                              void* d_out, int out_size) {
    const float* Tf0 = (const float*)d_in[0];
    const float* Tf1 = (const float*)d_in[1];
    const float* Sf0 = (const float*)d_in[2];
    const float* Sf1 = (const float*)d_in[3];
    const float* g0  = (const float*)d_in[4];
    const float* g1  = (const float*)d_in[5];
    float* out = (float*)d_out;

    float *w0, *w1, *pc0, *pt0, *ps0, *pc1, *pt1, *ps1;
    cudaGetSymbolAddress((void**)&w0,  d_w0);
    cudaGetSymbolAddress((void**)&w1,  d_w1);
    cudaGetSymbolAddress((void**)&pc0, d_pc0);
    cudaGetSymbolAddress((void**)&pt0, d_pt0);
    cudaGetSymbolAddress((void**)&ps0, d_ps0);
    cudaGetSymbolAddress((void**)&pc1, d_pc1);
    cudaGetSymbolAddress((void**)&pt1, d_pt1);
    cudaGetSymbolAddress((void**)&ps1, d_ps1);

    // Phase A: gmean + Sf sums, interleaved blocks (284 MB)
    k_phaseA<<<6400, 128>>>(g0, g1, Sf0, Sf1, w0, w1, ps0, ps1);

    // Phase B: Tf pass -> pc, pt (142 MB)
    {
        dim3 grid(3, B, NCH0 + NCH1);   // 2304 blocks of 128
        k_camT<<<grid, 128>>>(Tf0, w0, pc0, pt0, Tf1, w1, pc1, pt1);
    }

    // Phase C1: stats (cam/thr/fw) + unmasked emb combine, one launch
    k_finC1<<<246, 512>>>(pc0, pc1, pt0, ps0, pt1, ps1, out);

    // Phase C2: zero masked-out entries
    k_maskzero<<<226, 256>>>(out);
}